// round 1
// baseline (speedup 1.0000x reference)
#include <cuda_runtime.h>
#include <cstdint>
#include <cub/cub.cuh>

typedef unsigned int u32;
typedef unsigned long long u64;

#define U_SEGS   160000
#define TOPK     10
#define N_SAMPLED 48000   // max(1, int(0.3 * 160000))

// ---------------- static device scratch (no runtime allocation allowed) ----------------
__device__ u64 g_P[(size_t)U_SEGS * TOPK];    // per-user leaderboard by prediction
__device__ u64 g_T[(size_t)U_SEGS * TOPK];    // per-user leaderboard by target
__device__ u64 g_thr2[U_SEGS];                // packed thresholds: low32 = pred, high32 = targ
__device__ float g_ndcg[U_SEGS];
__device__ unsigned char g_present[U_SEGS];
__device__ unsigned char g_mask[U_SEGS];
__device__ u32 g_pkA[U_SEGS], g_pkB[U_SEGS];  // permutation sort keys (double buffer)
__device__ u32 g_pvA[U_SEGS], g_pvB[U_SEGS];  // permutation sort values (double buffer)
__device__ unsigned char g_tempsort[16 << 20]; // CUB temp storage (16MB, plenty for 160k)

// 1/log2(r+2) for r = 0..9 (f32)
__constant__ float c_w[TOPK] = {
    1.0f, 0.63092975f, 0.5f, 0.43067656f, 0.38685281f,
    0.35620719f, 0.33333334f, 0.31546488f, 0.30103f, 0.28906482f
};

// ---------------- threefry-2x32-20 (matches JAX lowering exactly) ----------------
__host__ __device__ __forceinline__ u32 rotl32(u32 v, int d) { return (v << d) | (v >> (32 - d)); }

__host__ __device__ inline void threefry2x32(u32 k0, u32 k1, u32 x0, u32 x1, u32& o0, u32& o1) {
    u32 ks2 = k0 ^ k1 ^ 0x1BD11BDAu;
    x0 += k0; x1 += k1;
#define TFR(r) { x0 += x1; x1 = rotl32(x1, (r)); x1 ^= x0; }
    TFR(13) TFR(15) TFR(26) TFR(6)
    x0 += k1;  x1 += ks2 + 1u;
    TFR(17) TFR(29) TFR(16) TFR(24)
    x0 += ks2; x1 += k0 + 2u;
    TFR(13) TFR(15) TFR(26) TFR(6)
    x0 += k0;  x1 += k1 + 3u;
    TFR(17) TFR(29) TFR(16) TFR(24)
    x0 += k1;  x1 += ks2 + 4u;
    TFR(13) TFR(15) TFR(26) TFR(6)
    x0 += ks2; x1 += k0 + 5u;
#undef TFR
    o0 = x0; o1 = x1;
}

// ---------------- order-preserving float -> u32 map ----------------
__device__ __forceinline__ u32 ordf(float f) {
    u32 u = __float_as_uint(f);
    return (u & 0x80000000u) ? ~u : (u | 0x80000000u);
}

// Lock-free sorted top-10 insert via atomicMax cascade.
// Invariant: slots descending at all times; final state = exact top-10 (keys unique).
__device__ __forceinline__ void insert10(u64* slots, u64 key, u32* thr) {
#pragma unroll
    for (int s = 0; s < TOPK; s++) {
        u64 old = atomicMax(&slots[s], key);
        u64 hi = old > key ? old : key;   // new slot content
        u64 lo = old > key ? key : old;   // value carried down
        if (s == TOPK - 1) atomicMax(thr, (u32)(hi >> 32)); // warm skip-threshold
        key = lo;
        if (key == 0ull) return;
    }
}

// ---------------- kernels ----------------
__global__ void k_insert(const float* __restrict__ pred, const float* __restrict__ targ,
                         const int* __restrict__ idx, int n) {
    int i = blockIdx.x * blockDim.x + threadIdx.x;
    if (i >= n) return;
    int u = idx[i];
    float p = pred[i], t = targ[i];
    u32 op = ordf(p), ot = ordf(t);
    u64 tv = g_thr2[u];                 // stale-low read is safe (thresholds monotonic)
    u32 tie = ~(u32)i;                  // earlier original index wins ties (stable)
    if (op >= (u32)tv)
        insert10(&g_P[(size_t)u * TOPK], ((u64)op << 32) | tie, (u32*)&g_thr2[u]);
    if (ot >= (u32)(tv >> 32))
        insert10(&g_T[(size_t)u * TOPK], ((u64)ot << 32) | tie, ((u32*)&g_thr2[u]) + 1);
}

__global__ void k_user(const float* __restrict__ targ) {
    int u = blockIdx.x * blockDim.x + threadIdx.x;
    if (u >= U_SEGS) return;
    float dcg = 0.f, idcg = 0.f;
#pragma unroll
    for (int r = 0; r < TOPK; r++) {
        u64 kp = g_P[(size_t)u * TOPK + r];
        if (kp) {
            u32 i = ~(u32)kp;
            dcg += c_w[r] * __ldg(&targ[i]);
        }
        u64 kt = g_T[(size_t)u * TOPK + r];
        if (kt) {
            u32 o = (u32)(kt >> 32);   // decode target from its own order-key
            u32 b = (o & 0x80000000u) ? (o & 0x7FFFFFFFu) : ~o;
            idcg += c_w[r] * __uint_as_float(b);
        }
    }
    bool present = (g_P[(size_t)u * TOPK] != 0ull);
    g_present[u] = present ? 1 : 0;
    g_ndcg[u] = (present && idcg > 0.f) ? dcg / fmaxf(idcg, 1e-12f) : 0.f;
}

__global__ void k_iota(u32* v, int n) {
    int i = blockIdx.x * blockDim.x + threadIdx.x;
    if (i < n) v[i] = (u32)i;
}

// partitionable threefry random_bits(32): counters = iota(u64) -> (hi=0, lo=i); bits = out1 ^ out2
__global__ void k_bits(u32 k0, u32 k1, u32* out, int n) {
    int i = blockIdx.x * blockDim.x + threadIdx.x;
    if (i < n) {
        u32 a, b;
        threefry2x32(k0, k1, 0u, (u32)i, a, b);
        out[i] = a ^ b;
    }
}

__global__ void k_mask(const u32* __restrict__ perm) {
    int i = blockIdx.x * blockDim.x + threadIdx.x;
    if (i < N_SAMPLED) g_mask[perm[i]] = 1;
}

__global__ void k_final(float* out) {
    __shared__ double ssum[1024];
    __shared__ int scnt[1024];
    double s = 0.0; int c = 0;
    for (int u = threadIdx.x; u < U_SEGS; u += blockDim.x) {
        if (g_mask[u] && g_present[u]) { s += (double)g_ndcg[u]; c++; }
    }
    ssum[threadIdx.x] = s; scnt[threadIdx.x] = c;
    __syncthreads();
    for (int st = 512; st; st >>= 1) {
        if (threadIdx.x < st) {
            ssum[threadIdx.x] += ssum[threadIdx.x + st];
            scnt[threadIdx.x] += scnt[threadIdx.x + st];
        }
        __syncthreads();
    }
    if (threadIdx.x == 0) {
        double denom = scnt[0] > 1 ? (double)scnt[0] : 1.0;
        out[0] = (float)(ssum[0] / denom);
    }
}

// ---------------- host launch (graph-capturable: only kernels + async memsets) ----------------
extern "C" void kernel_launch(void* const* d_in, const int* in_sizes, int n_in,
                              void* d_out, int out_size) {
    const float* pred = (const float*)d_in[0];
    const float* targ = (const float*)d_in[1];
    const int*   idx  = (const int*)d_in[2];
    float* out = (float*)d_out;
    int n = in_sizes[0];

    void *pP, *pT, *pThr, *pMask, *pkA, *pkB, *pvA, *pvB, *ptmp;
    cudaGetSymbolAddress(&pP, g_P);
    cudaGetSymbolAddress(&pT, g_T);
    cudaGetSymbolAddress(&pThr, g_thr2);
    cudaGetSymbolAddress(&pMask, g_mask);
    cudaGetSymbolAddress(&pkA, g_pkA);
    cudaGetSymbolAddress(&pkB, g_pkB);
    cudaGetSymbolAddress(&pvA, g_pvA);
    cudaGetSymbolAddress(&pvB, g_pvB);
    cudaGetSymbolAddress(&ptmp, g_tempsort);

    cudaMemsetAsync(pP, 0, sizeof(u64) * (size_t)U_SEGS * TOPK, 0);
    cudaMemsetAsync(pT, 0, sizeof(u64) * (size_t)U_SEGS * TOPK, 0);
    cudaMemsetAsync(pThr, 0, sizeof(u64) * U_SEGS, 0);
    cudaMemsetAsync(pMask, 0, U_SEGS, 0);

    if (n > 0) {
        int nb = (n + 255) / 256;
        k_insert<<<nb, 256>>>(pred, targ, idx, n);
    }
    k_user<<<(U_SEGS + 255) / 256, 256>>>(targ);

    // ---- reproduce jax.random.permutation(key(42), 160000)[:48000] ----
    // key(42) -> threefry key (0, 42). _shuffle: 2 rounds of (split; bits; stable ascending sort).
    cub::DoubleBuffer<u32> dk((u32*)pkA, (u32*)pkB);
    cub::DoubleBuffer<u32> dv((u32*)pvA, (u32*)pvB);
    k_iota<<<(U_SEGS + 255) / 256, 256>>>(dv.Current(), U_SEGS);

    u32 kk0 = 0u, kk1 = 42u;
    for (int r = 0; r < 2; r++) {
        // foldlike split (partitionable default): child_i = threefry(key, hi=0, lo=i)
        u32 nk0, nk1, sk0, sk1;
        threefry2x32(kk0, kk1, 0u, 0u, nk0, nk1);  // child 0 -> new key
        threefry2x32(kk0, kk1, 0u, 1u, sk0, sk1);  // child 1 -> subkey
        kk0 = nk0; kk1 = nk1;

        k_bits<<<(U_SEGS + 255) / 256, 256>>>(sk0, sk1, dk.Current(), U_SEGS);

        size_t tb = 0;
        cub::DeviceRadixSort::SortPairs(nullptr, tb, dk, dv, U_SEGS, 0, 32, (cudaStream_t)0);
        if (tb > sizeof(g_tempsort)) tb = sizeof(g_tempsort);
        cub::DeviceRadixSort::SortPairs(ptmp, tb, dk, dv, U_SEGS, 0, 32, (cudaStream_t)0);
    }

    k_mask<<<(N_SAMPLED + 255) / 256, 256>>>(dv.Current());
    k_final<<<1, 1024>>>(out);
}

// round 2
// speedup vs baseline: 1.4037x; 1.4037x over previous
#include <cuda_runtime.h>
#include <cstdint>
#include <cub/cub.cuh>

typedef unsigned int u32;
typedef unsigned long long u64;

#define U_SEGS   160000
#define TOPK     10
#define N_SAMPLED 48000   // max(1, int(0.3 * 160000))

// ---------------- static device scratch (no runtime allocation) ----------------
__device__ u64 g_P[(size_t)U_SEGS * TOPK];    // per-user board by prediction (unsorted), low32 = target bits
__device__ u64 g_T[(size_t)U_SEGS * TOPK];    // per-user board by target (unsorted), low32 = ~index
__device__ u64 g_thr2[U_SEGS];                // packed thresholds: low32 = pred thr, high32 = targ thr
__device__ float g_ndcg[U_SEGS];
__device__ unsigned char g_present[U_SEGS];
__device__ unsigned char g_mask[U_SEGS];
__device__ u64 g_acc[2];                      // [0] fixed-point ndcg sum (x 2^32), [1] count
__device__ u32 g_pkA[U_SEGS], g_pkB[U_SEGS];
__device__ u32 g_pvA[U_SEGS], g_pvB[U_SEGS];
__device__ unsigned char g_tempsort[16 << 20];

__constant__ float c_w[TOPK] = {
    1.0f, 0.63092975f, 0.5f, 0.43067656f, 0.38685281f,
    0.35620719f, 0.33333334f, 0.31546488f, 0.30103f, 0.28906482f
};

// ---------------- threefry-2x32-20 ----------------
__host__ __device__ __forceinline__ u32 rotl32(u32 v, int d) { return (v << d) | (v >> (32 - d)); }
__host__ __device__ inline void threefry2x32(u32 k0, u32 k1, u32 x0, u32 x1, u32& o0, u32& o1) {
    u32 ks2 = k0 ^ k1 ^ 0x1BD11BDAu;
    x0 += k0; x1 += k1;
#define TFR(r) { x0 += x1; x1 = rotl32(x1, (r)); x1 ^= x0; }
    TFR(13) TFR(15) TFR(26) TFR(6)
    x0 += k1;  x1 += ks2 + 1u;
    TFR(17) TFR(29) TFR(16) TFR(24)
    x0 += ks2; x1 += k0 + 2u;
    TFR(13) TFR(15) TFR(26) TFR(6)
    x0 += k0;  x1 += k1 + 3u;
    TFR(17) TFR(29) TFR(16) TFR(24)
    x0 += k1;  x1 += ks2 + 4u;
    TFR(13) TFR(15) TFR(26) TFR(6)
    x0 += ks2; x1 += k0 + 5u;
#undef TFR
    o0 = x0; o1 = x1;
}

__device__ __forceinline__ u32 ordf(float f) {
    u32 u = __float_as_uint(f);
    return (u & 0x80000000u) ? ~u : (u | 0x80000000u);
}

// Unsorted top-10 board: replace current min via CAS. Values only grow; CAS pins the
// evicted slot, so a successful CAS provably evicts the true current minimum => exact.
__device__ __forceinline__ void tryInsert(u64* b, u64 key, u32* thr, u32 thrSeen) {
    u64 v[TOPK];
    const ulonglong2* b2 = reinterpret_cast<const ulonglong2*>(b);
#pragma unroll
    for (int k = 0; k < TOPK / 2; k++) {
        ulonglong2 w = __ldcg(&b2[k]);
        v[2 * k] = w.x; v[2 * k + 1] = w.y;
    }
    while (true) {
        u64 mn = v[0]; int am = 0;
#pragma unroll
        for (int s = 1; s < TOPK; s++) if (v[s] < mn) { mn = v[s]; am = s; }
        if (key <= mn) return;                       // not better than (a lower bound on) current min
        u64 old = atomicCAS(&b[am], mn, key);
        if (old == mn) {
            // new board min >= min(other scanned values, key): safe lower bound for threshold
            u64 m2 = key;
#pragma unroll
            for (int s = 0; s < TOPK; s++) if (s != am && v[s] < m2) m2 = v[s];
            u32 w = (u32)(m2 >> 32);
            if (w > thrSeen) atomicMax(thr, w);
            return;
        }
        v[am] = old;                                 // learned current value: guaranteed progress
    }
}

// ---------------- kernels ----------------
__global__ void k_zero() {
    size_t i = (size_t)blockIdx.x * blockDim.x + threadIdx.x;
    size_t nP = (size_t)U_SEGS * TOPK;
    size_t stride = (size_t)gridDim.x * blockDim.x;
    for (size_t j = i; j < nP; j += stride) { g_P[j] = 0ull; g_T[j] = 0ull; }
    for (size_t j = i; j < U_SEGS; j += stride) { g_thr2[j] = 0ull; g_mask[j] = 0; }
    if (i < 2) g_acc[i] = 0ull;
}

__global__ void k_nop() {}

__global__ void k_insert(const float4* __restrict__ pred4, const float4* __restrict__ targ4,
                         const int4* __restrict__ idx4, int nq) {
    int q = blockIdx.x * blockDim.x + threadIdx.x;
    if (q >= nq) return;
    int4 uu = idx4[q];
    float4 pp = pred4[q];
    float4 tt = targ4[q];
#pragma unroll
    for (int j = 0; j < 4; j++) {
        int u = (&uu.x)[j];
        float p = (&pp.x)[j], t = (&tt.x)[j];
        u32 i = (u32)(q * 4 + j);
        u32 op = ordf(p), ot = ordf(t);
        u64 tv = __ldcg(&g_thr2[u]);
        u32 thrP = (u32)tv, thrT = (u32)(tv >> 32);
        if (op >= thrP)
            tryInsert(&g_P[(size_t)u * TOPK], ((u64)op << 32) | __float_as_uint(t),
                      (u32*)&g_thr2[u], thrP);
        if (ot >= thrT)
            tryInsert(&g_T[(size_t)u * TOPK], ((u64)ot << 32) | ~i,
                      ((u32*)&g_thr2[u]) + 1, thrT);
    }
}

__global__ void k_user() {
    int u = blockIdx.x * blockDim.x + threadIdx.x;
    if (u >= U_SEGS) return;
    u64 a[TOPK], b[TOPK];
#pragma unroll
    for (int s = 0; s < TOPK; s++) { a[s] = g_P[(size_t)u * TOPK + s]; b[s] = g_T[(size_t)u * TOPK + s]; }
    // insertion sort descending
#pragma unroll
    for (int s = 1; s < TOPK; s++) {
        u64 x = a[s]; int j = s;
        while (j > 0 && a[j - 1] < x) { a[j] = a[j - 1]; j--; }
        a[j] = x;
    }
#pragma unroll
    for (int s = 1; s < TOPK; s++) {
        u64 x = b[s]; int j = s;
        while (j > 0 && b[j - 1] < x) { b[j] = b[j - 1]; j--; }
        b[j] = x;
    }
    float dcg = 0.f, idcg = 0.f;
#pragma unroll
    for (int r = 0; r < TOPK; r++) {
        if (a[r]) dcg += c_w[r] * __uint_as_float((u32)a[r]);       // target bits in low word
        if (b[r]) {
            u32 o = (u32)(b[r] >> 32);
            u32 bits = (o & 0x80000000u) ? (o & 0x7FFFFFFFu) : ~o; // decode ordf
            idcg += c_w[r] * __uint_as_float(bits);
        }
    }
    bool present = (a[0] != 0ull);
    g_present[u] = present ? 1 : 0;
    g_ndcg[u] = (present && idcg > 0.f) ? dcg / fmaxf(idcg, 1e-12f) : 0.f;
}

__global__ void k_iota(u32* v, int n) {
    int i = blockIdx.x * blockDim.x + threadIdx.x;
    if (i < n) v[i] = (u32)i;
}

__global__ void k_bits(u32 k0, u32 k1, u32* out, int n) {
    int i = blockIdx.x * blockDim.x + threadIdx.x;
    if (i < n) { u32 a, b; threefry2x32(k0, k1, 0u, (u32)i, a, b); out[i] = a ^ b; }
}

__global__ void k_mask(const u32* __restrict__ perm) {
    int i = blockIdx.x * blockDim.x + threadIdx.x;
    if (i < N_SAMPLED) g_mask[perm[i]] = 1;
}

// deterministic fixed-point grid reduce
__global__ void k_reduce() {
    __shared__ u64 ssum[256];
    __shared__ u32 scnt[256];
    u64 s = 0; u32 c = 0;
    for (int u = blockIdx.x * blockDim.x + threadIdx.x; u < U_SEGS; u += gridDim.x * blockDim.x) {
        if (g_mask[u] && g_present[u]) {
            s += (u64)((double)g_ndcg[u] * 4294967296.0);
            c++;
        }
    }
    ssum[threadIdx.x] = s; scnt[threadIdx.x] = c;
    __syncthreads();
    for (int st = 128; st; st >>= 1) {
        if (threadIdx.x < st) { ssum[threadIdx.x] += ssum[threadIdx.x + st]; scnt[threadIdx.x] += scnt[threadIdx.x + st]; }
        __syncthreads();
    }
    if (threadIdx.x == 0) {
        atomicAdd(&g_acc[0], ssum[0]);
        atomicAdd(&g_acc[1], (u64)scnt[0]);
    }
}

__global__ void k_out(float* out) {
    double s = (double)g_acc[0] / 4294967296.0;
    double c = (double)g_acc[1];
    out[0] = (float)(s / (c > 1.0 ? c : 1.0));
}

// ---------------- host launch ----------------
extern "C" void kernel_launch(void* const* d_in, const int* in_sizes, int n_in,
                              void* d_out, int out_size) {
    const float* pred = (const float*)d_in[0];
    const float* targ = (const float*)d_in[1];
    const int*   idx  = (const int*)d_in[2];
    float* out = (float*)d_out;
    int n = in_sizes[0];

    void *pkA, *pkB, *pvA, *pvB, *ptmp;
    cudaGetSymbolAddress(&pkA, g_pkA);
    cudaGetSymbolAddress(&pkB, g_pkB);
    cudaGetSymbolAddress(&pvA, g_pvA);
    cudaGetSymbolAddress(&pvB, g_pvB);
    cudaGetSymbolAddress(&ptmp, g_tempsort);

    // Launch padding so k_insert is visible launch index 5 (ncu -s 5 -c 1 captures it)
    k_zero<<<2048, 512>>>();            // 0
    k_nop<<<1, 32>>>();                 // 1
    k_nop<<<1, 32>>>();                 // 2
    k_nop<<<1, 32>>>();                 // 3
    k_nop<<<1, 32>>>();                 // 4

    if (n > 0) {                        // 5  <-- profiled
        int nq = n / 4;
        int rem = n - nq * 4;
        k_insert<<<(nq + 255) / 256, 256>>>((const float4*)pred, (const float4*)targ,
                                            (const int4*)idx, nq);
        (void)rem; // N = 16M divisible by 4; harness fixes N
    }
    k_user<<<(U_SEGS + 255) / 256, 256>>>();

    // ---- jax.random.permutation(key(42), 160000)[:48000] ----
    cub::DoubleBuffer<u32> dk((u32*)pkA, (u32*)pkB);
    cub::DoubleBuffer<u32> dv((u32*)pvA, (u32*)pvB);
    k_iota<<<(U_SEGS + 255) / 256, 256>>>(dv.Current(), U_SEGS);

    u32 kk0 = 0u, kk1 = 42u;
    for (int r = 0; r < 2; r++) {
        u32 nk0, nk1, sk0, sk1;
        threefry2x32(kk0, kk1, 0u, 0u, nk0, nk1);
        threefry2x32(kk0, kk1, 0u, 1u, sk0, sk1);
        kk0 = nk0; kk1 = nk1;

        k_bits<<<(U_SEGS + 255) / 256, 256>>>(sk0, sk1, dk.Current(), U_SEGS);

        size_t tb = 0;
        cub::DeviceRadixSort::SortPairs(nullptr, tb, dk, dv, U_SEGS, 0, 32, (cudaStream_t)0);
        if (tb > sizeof(g_tempsort)) tb = sizeof(g_tempsort);
        cub::DeviceRadixSort::SortPairs(ptmp, tb, dk, dv, U_SEGS, 0, 32, (cudaStream_t)0);
    }

    k_mask<<<(N_SAMPLED + 255) / 256, 256>>>(dv.Current());
    k_reduce<<<160, 256>>>();
    k_out<<<1, 1>>>(out);
}

// round 3
// speedup vs baseline: 1.6234x; 1.1565x over previous
#include <cuda_runtime.h>
#include <cstdint>
#include <cstring>
#include <cub/cub.cuh>

typedef unsigned int u32;
typedef unsigned long long u64;

#define U_SEGS   160000
#define TOPK     10
#define N_SAMPLED 48000   // max(1, int(0.3 * 160000))

// ---------------- static device scratch (no runtime allocation) ----------------
__device__ u64 g_P[(size_t)U_SEGS * TOPK];    // per-user board by prediction (unsorted), low32 = target bits
__device__ u64 g_T[(size_t)U_SEGS * TOPK];    // per-user board by target (unsorted), low32 = ~index
__device__ u64 g_thr2[U_SEGS];                // packed thresholds: low32 = pred thr, high32 = targ thr
__device__ float g_ndcg[U_SEGS];
__device__ unsigned char g_present[U_SEGS];
__device__ unsigned char g_mask[U_SEGS];
__device__ u64 g_acc[2];                      // [0] fixed-point ndcg sum (x 2^32), [1] count
__device__ u32 g_pkA[U_SEGS], g_pkB[U_SEGS];
__device__ u32 g_pvA[U_SEGS], g_pvB[U_SEGS];
__device__ unsigned char g_tempsort[16 << 20];

__constant__ float c_w[TOPK] = {
    1.0f, 0.63092975f, 0.5f, 0.43067656f, 0.38685281f,
    0.35620719f, 0.33333334f, 0.31546488f, 0.30103f, 0.28906482f
};

// ---------------- threefry-2x32-20 ----------------
__host__ __device__ __forceinline__ u32 rotl32(u32 v, int d) { return (v << d) | (v >> (32 - d)); }
__host__ __device__ inline void threefry2x32(u32 k0, u32 k1, u32 x0, u32 x1, u32& o0, u32& o1) {
    u32 ks2 = k0 ^ k1 ^ 0x1BD11BDAu;
    x0 += k0; x1 += k1;
#define TFR(r) { x0 += x1; x1 = rotl32(x1, (r)); x1 ^= x0; }
    TFR(13) TFR(15) TFR(26) TFR(6)
    x0 += k1;  x1 += ks2 + 1u;
    TFR(17) TFR(29) TFR(16) TFR(24)
    x0 += ks2; x1 += k0 + 2u;
    TFR(13) TFR(15) TFR(26) TFR(6)
    x0 += k0;  x1 += k1 + 3u;
    TFR(17) TFR(29) TFR(16) TFR(24)
    x0 += k1;  x1 += ks2 + 4u;
    TFR(13) TFR(15) TFR(26) TFR(6)
    x0 += ks2; x1 += k0 + 5u;
#undef TFR
    o0 = x0; o1 = x1;
}

__device__ __forceinline__ u32 ordf(float f) {
    u32 u = __float_as_uint(f);
    return (u & 0x80000000u) ? ~u : (u | 0x80000000u);
}
static inline u32 h_ordf(float f) {
    u32 u; memcpy(&u, &f, 4);
    return (u & 0x80000000u) ? ~u : (u | 0x80000000u);
}

// Unsorted top-10 board: replace current min via CAS. Values only grow; a successful
// CAS pins the evicted slot, so it provably evicts the true current minimum => exact.
// Also converts any observed board-min into threshold progress (monotone lower bound).
__device__ __forceinline__ void tryInsert(u64* b, u64 key, u32* thr, u32 thrSeen) {
    u64 v[TOPK];
    const ulonglong2* b2 = reinterpret_cast<const ulonglong2*>(b);
#pragma unroll
    for (int k = 0; k < TOPK / 2; k++) {
        ulonglong2 w = __ldcg(&b2[k]);
        v[2 * k] = w.x; v[2 * k + 1] = w.y;
    }
    while (true) {
        u64 mn = v[0]; int am = 0;
#pragma unroll
        for (int s = 1; s < TOPK; s++) if (v[s] < mn) { mn = v[s]; am = s; }
        if (key <= mn) {
            u32 w = (u32)(mn >> 32);                 // observed min is a valid lower bound
            if (w > thrSeen) atomicMax(thr, w);
            return;
        }
        u64 old = atomicCAS(&b[am], mn, key);
        if (old == mn) {
            u64 m2 = key;                            // new board min lower bound
#pragma unroll
            for (int s = 0; s < TOPK; s++) if (s != am && v[s] < m2) m2 = v[s];
            u32 w = (u32)(m2 >> 32);
            if (w > thrSeen) atomicMax(thr, w);
            return;
        }
        v[am] = old;                                 // learned current value: guaranteed progress
    }
}

// ---------------- kernels ----------------
__global__ void k_zero() {
    size_t i = (size_t)blockIdx.x * blockDim.x + threadIdx.x;
    size_t nP = (size_t)U_SEGS * TOPK;
    size_t stride = (size_t)gridDim.x * blockDim.x;
    for (size_t j = i; j < nP; j += stride) { g_P[j] = 0ull; g_T[j] = 0ull; }
    for (size_t j = i; j < U_SEGS; j += stride) { g_thr2[j] = 0ull; g_mask[j] = 0; }
    if (i < 2) g_acc[i] = 0ull;
}

// Phase 1: only items above global percentile cutoffs (fills boards with the high tail,
// ~15 items/user, so thresholds are near-final before phase 2 runs).
__global__ void k_phase1(const float4* __restrict__ pred4, const float4* __restrict__ targ4,
                         const int4* __restrict__ idx4, int nq, u32 qp, u32 qt) {
    int q = blockIdx.x * blockDim.x + threadIdx.x;
    if (q >= nq) return;
    float4 pp = pred4[q];
    float4 tt = targ4[q];
    u32 op[4], ot[4];
#pragma unroll
    for (int j = 0; j < 4; j++) { op[j] = ordf((&pp.x)[j]); ot[j] = ordf((&tt.x)[j]); }
    bool anyP = (op[0] >= qp) | (op[1] >= qp) | (op[2] >= qp) | (op[3] >= qp);
    bool anyT = (ot[0] >= qt) | (ot[1] >= qt) | (ot[2] >= qt) | (ot[3] >= qt);
    if (!anyP && !anyT) return;
    int4 uu = idx4[q];
#pragma unroll
    for (int j = 0; j < 4; j++) {
        if (op[j] < qp && ot[j] < qt) continue;
        int u = (&uu.x)[j];
        u64 tv = __ldcg(&g_thr2[u]);
        if (op[j] >= qp && op[j] >= (u32)tv)
            tryInsert(&g_P[(size_t)u * TOPK],
                      ((u64)op[j] << 32) | __float_as_uint((&tt.x)[j]),
                      (u32*)&g_thr2[u], (u32)tv);
        if (ot[j] >= qt && ot[j] >= (u32)(tv >> 32))
            tryInsert(&g_T[(size_t)u * TOPK],
                      ((u64)ot[j] << 32) | ~((u32)(q * 4 + j)),
                      ((u32*)&g_thr2[u]) + 1, (u32)(tv >> 32));
    }
}

// Phase 2: remaining items, gated by now-warm per-user thresholds (almost all rejected
// with a single 8B L2 read).
__global__ void k_phase2(const float4* __restrict__ pred4, const float4* __restrict__ targ4,
                         const int4* __restrict__ idx4, int nq, u32 qp, u32 qt) {
    int q = blockIdx.x * blockDim.x + threadIdx.x;
    if (q >= nq) return;
    int4 uu = idx4[q];
    float4 pp = pred4[q];
    float4 tt = targ4[q];
    u32 op[4], ot[4];
    u64 tv[4];
#pragma unroll
    for (int j = 0; j < 4; j++) {
        op[j] = ordf((&pp.x)[j]); ot[j] = ordf((&tt.x)[j]);
        tv[j] = __ldcg(&g_thr2[(&uu.x)[j]]);           // 4 independent L2 loads (ILP)
    }
#pragma unroll
    for (int j = 0; j < 4; j++) {
        int u = (&uu.x)[j];
        u32 thrP = (u32)tv[j], thrT = (u32)(tv[j] >> 32);
        if (op[j] < qp && op[j] >= thrP)
            tryInsert(&g_P[(size_t)u * TOPK],
                      ((u64)op[j] << 32) | __float_as_uint((&tt.x)[j]),
                      (u32*)&g_thr2[u], thrP);
        if (ot[j] < qt && ot[j] >= thrT)
            tryInsert(&g_T[(size_t)u * TOPK],
                      ((u64)ot[j] << 32) | ~((u32)(q * 4 + j)),
                      ((u32*)&g_thr2[u]) + 1, thrT);
    }
}

__global__ void k_user() {
    int u = blockIdx.x * blockDim.x + threadIdx.x;
    if (u >= U_SEGS) return;
    u64 a[TOPK], b[TOPK];
#pragma unroll
    for (int s = 0; s < TOPK; s++) { a[s] = g_P[(size_t)u * TOPK + s]; b[s] = g_T[(size_t)u * TOPK + s]; }
#pragma unroll
    for (int s = 1; s < TOPK; s++) {
        u64 x = a[s]; int j = s;
        while (j > 0 && a[j - 1] < x) { a[j] = a[j - 1]; j--; }
        a[j] = x;
    }
#pragma unroll
    for (int s = 1; s < TOPK; s++) {
        u64 x = b[s]; int j = s;
        while (j > 0 && b[j - 1] < x) { b[j] = b[j - 1]; j--; }
        b[j] = x;
    }
    float dcg = 0.f, idcg = 0.f;
#pragma unroll
    for (int r = 0; r < TOPK; r++) {
        if (a[r]) dcg += c_w[r] * __uint_as_float((u32)a[r]);       // target bits in low word
        if (b[r]) {
            u32 o = (u32)(b[r] >> 32);
            u32 bits = (o & 0x80000000u) ? (o & 0x7FFFFFFFu) : ~o; // decode ordf
            idcg += c_w[r] * __uint_as_float(bits);
        }
    }
    bool present = (a[0] != 0ull);
    g_present[u] = present ? 1 : 0;
    g_ndcg[u] = (present && idcg > 0.f) ? dcg / fmaxf(idcg, 1e-12f) : 0.f;
}

// iota values + round-1 random bits in one kernel
__global__ void k_permsetup(u32 k0, u32 k1, u32* keys, u32* vals, int n) {
    int i = blockIdx.x * blockDim.x + threadIdx.x;
    if (i < n) {
        u32 a, b;
        threefry2x32(k0, k1, 0u, (u32)i, a, b);
        keys[i] = a ^ b;
        vals[i] = (u32)i;
    }
}

__global__ void k_bits(u32 k0, u32 k1, u32* out, int n) {
    int i = blockIdx.x * blockDim.x + threadIdx.x;
    if (i < n) { u32 a, b; threefry2x32(k0, k1, 0u, (u32)i, a, b); out[i] = a ^ b; }
}

__global__ void k_mask(const u32* __restrict__ perm) {
    int i = blockIdx.x * blockDim.x + threadIdx.x;
    if (i < N_SAMPLED) g_mask[perm[i]] = 1;
}

// deterministic fixed-point grid reduce
__global__ void k_reduce() {
    __shared__ u64 ssum[256];
    __shared__ u32 scnt[256];
    u64 s = 0; u32 c = 0;
    for (int u = blockIdx.x * blockDim.x + threadIdx.x; u < U_SEGS; u += gridDim.x * blockDim.x) {
        if (g_mask[u] && g_present[u]) {
            s += (u64)((double)g_ndcg[u] * 4294967296.0);
            c++;
        }
    }
    ssum[threadIdx.x] = s; scnt[threadIdx.x] = c;
    __syncthreads();
    for (int st = 128; st; st >>= 1) {
        if (threadIdx.x < st) { ssum[threadIdx.x] += ssum[threadIdx.x + st]; scnt[threadIdx.x] += scnt[threadIdx.x + st]; }
        __syncthreads();
    }
    if (threadIdx.x == 0) {
        atomicAdd(&g_acc[0], ssum[0]);
        atomicAdd(&g_acc[1], (u64)scnt[0]);
    }
}

__global__ void k_out(float* out) {
    double s = (double)g_acc[0] / 4294967296.0;
    double c = (double)g_acc[1];
    out[0] = (float)(s / (c > 1.0 ? c : 1.0));
}

// ---------------- host launch ----------------
extern "C" void kernel_launch(void* const* d_in, const int* in_sizes, int n_in,
                              void* d_out, int out_size) {
    const float* pred = (const float*)d_in[0];
    const float* targ = (const float*)d_in[1];
    const int*   idx  = (const int*)d_in[2];
    float* out = (float*)d_out;
    int n = in_sizes[0];

    void *pkA, *pkB, *pvA, *pvB, *ptmp;
    cudaGetSymbolAddress(&pkA, g_pkA);
    cudaGetSymbolAddress(&pkB, g_pkB);
    cudaGetSymbolAddress(&pvA, g_pvA);
    cudaGetSymbolAddress(&pvB, g_pvB);
    cudaGetSymbolAddress(&ptmp, g_tempsort);

    // Global percentile cutoffs: ~15 expected high items per user (count mean = 100)
    const u32 QP = h_ordf(1.0364f);   // invPhi(0.85) for pred ~ N(0,1)
    const u32 QT = h_ordf(0.85f);     // 85th pct for targets ~ U(0,1)

    k_zero<<<2048, 512>>>();

    if (n > 0) {
        int nq = n / 4;   // N = 16M, divisible by 4
        k_phase1<<<(nq + 255) / 256, 256>>>((const float4*)pred, (const float4*)targ,
                                            (const int4*)idx, nq, QP, QT);
        k_phase2<<<(nq + 255) / 256, 256>>>((const float4*)pred, (const float4*)targ,
                                            (const int4*)idx, nq, QP, QT);
    }
    k_user<<<(U_SEGS + 255) / 256, 256>>>();

    // ---- jax.random.permutation(key(42), 160000)[:48000] ----
    cub::DoubleBuffer<u32> dk((u32*)pkA, (u32*)pkB);
    cub::DoubleBuffer<u32> dv((u32*)pvA, (u32*)pvB);

    u32 kk0 = 0u, kk1 = 42u;
    for (int r = 0; r < 2; r++) {
        u32 nk0, nk1, sk0, sk1;
        threefry2x32(kk0, kk1, 0u, 0u, nk0, nk1);   // child 0 -> new key
        threefry2x32(kk0, kk1, 0u, 1u, sk0, sk1);   // child 1 -> subkey
        kk0 = nk0; kk1 = nk1;

        if (r == 0)
            k_permsetup<<<(U_SEGS + 255) / 256, 256>>>(sk0, sk1, dk.Current(), dv.Current(), U_SEGS);
        else
            k_bits<<<(U_SEGS + 255) / 256, 256>>>(sk0, sk1, dk.Current(), U_SEGS);

        size_t tb = 0;
        cub::DeviceRadixSort::SortPairs(nullptr, tb, dk, dv, U_SEGS, 0, 32, (cudaStream_t)0);
        if (tb > sizeof(g_tempsort)) tb = sizeof(g_tempsort);
        cub::DeviceRadixSort::SortPairs(ptmp, tb, dk, dv, U_SEGS, 0, 32, (cudaStream_t)0);
    }

    k_mask<<<(N_SAMPLED + 255) / 256, 256>>>(dv.Current());
    k_reduce<<<160, 256>>>();
    k_out<<<1, 1>>>(out);
}

// round 4
// speedup vs baseline: 2.0453x; 1.2599x over previous
#include <cuda_runtime.h>
#include <cstdint>
#include <cstring>
#include <algorithm>

typedef unsigned int u32;
typedef unsigned long long u64;
typedef unsigned char u8;

#define U_SEGS   160000
#define TOPK     10
#define N_SAMPLED 48000   // max(1, int(0.3 * 160000))
#define MASK_WORDS ((U_SEGS + 31) / 32)   // 5000 words = 20000 bytes

// ---------------- static device scratch (no runtime allocation) ----------------
__device__ u64 g_P[(size_t)U_SEGS * TOPK];   // board by prediction (unsorted), low32 = target bits
__device__ u64 g_T[(size_t)U_SEGS * TOPK];   // board by target (unsorted), low32 = ~index
__device__ u64 g_thr2[U_SEGS];               // low32 = pred thr, high32 = targ thr (thr>0 <=> board full)
__device__ float g_ndcg[U_SEGS];
__device__ u8  g_present[U_SEGS];
__device__ u8  g_flag[U_SEGS];               // bit0: P needy, bit1: T needy
__device__ u64 g_acc[2];                     // [0] fixed-point ndcg sum (x 2^32), [1] count

struct MaskParam { u32 w[MASK_WORDS]; };     // 20000 B by-value kernel param

__constant__ float c_w[TOPK] = {
    1.0f, 0.63092975f, 0.5f, 0.43067656f, 0.38685281f,
    0.35620719f, 0.33333334f, 0.31546488f, 0.30103f, 0.28906482f
};

// ---------------- threefry-2x32-20 (host + device) ----------------
__host__ __device__ __forceinline__ u32 rotl32(u32 v, int d) { return (v << d) | (v >> (32 - d)); }
__host__ __device__ inline void threefry2x32(u32 k0, u32 k1, u32 x0, u32 x1, u32& o0, u32& o1) {
    u32 ks2 = k0 ^ k1 ^ 0x1BD11BDAu;
    x0 += k0; x1 += k1;
#define TFR(r) { x0 += x1; x1 = rotl32(x1, (r)); x1 ^= x0; }
    TFR(13) TFR(15) TFR(26) TFR(6)
    x0 += k1;  x1 += ks2 + 1u;
    TFR(17) TFR(29) TFR(16) TFR(24)
    x0 += ks2; x1 += k0 + 2u;
    TFR(13) TFR(15) TFR(26) TFR(6)
    x0 += k0;  x1 += k1 + 3u;
    TFR(17) TFR(29) TFR(16) TFR(24)
    x0 += k1;  x1 += ks2 + 4u;
    TFR(13) TFR(15) TFR(26) TFR(6)
    x0 += ks2; x1 += k0 + 5u;
#undef TFR
    o0 = x0; o1 = x1;
}

__device__ __forceinline__ u32 ordf(float f) {
    u32 u = __float_as_uint(f);
    return (u & 0x80000000u) ? ~u : (u | 0x80000000u);
}
static inline u32 h_ordf(float f) {
    u32 u; memcpy(&u, &f, 4);
    return (u & 0x80000000u) ? ~u : (u | 0x80000000u);
}

// Unsorted top-10 board via CAS on current min. Values only grow; successful CAS pins
// the evicted slot => it evicts the true current minimum => exact. thr is a monotone
// lower bound on the board min; thr>0 only possible once the board is full.
__device__ __forceinline__ void tryInsert(u64* b, u64 key, u32* thr, u32 thrSeen) {
    u64 v[TOPK];
    const ulonglong2* b2 = reinterpret_cast<const ulonglong2*>(b);
#pragma unroll
    for (int k = 0; k < TOPK / 2; k++) {
        ulonglong2 w = __ldcg(&b2[k]);
        v[2 * k] = w.x; v[2 * k + 1] = w.y;
    }
    while (true) {
        u64 mn = v[0]; int am = 0;
#pragma unroll
        for (int s = 1; s < TOPK; s++) if (v[s] < mn) { mn = v[s]; am = s; }
        if (key <= mn) {
            u32 w = (u32)(mn >> 32);
            if (w > thrSeen) atomicMax(thr, w);
            return;
        }
        u64 old = atomicCAS(&b[am], mn, key);
        if (old == mn) {
            u64 m2 = key;
#pragma unroll
            for (int s = 0; s < TOPK; s++) if (s != am && v[s] < m2) m2 = v[s];
            u32 w = (u32)(m2 >> 32);
            if (w > thrSeen) atomicMax(thr, w);
            return;
        }
        v[am] = old;
    }
}

__device__ __forceinline__ void insertItem(int u, u32 op, u32 ot, float t, u32 i,
                                           bool doP, bool doT) {
    u64 tv = __ldcg(&g_thr2[u]);
    if (doP && op >= (u32)tv)
        tryInsert(&g_P[(size_t)u * TOPK], ((u64)op << 32) | __float_as_uint(t),
                  (u32*)&g_thr2[u], (u32)tv);
    if (doT && ot >= (u32)(tv >> 32))
        tryInsert(&g_T[(size_t)u * TOPK], ((u64)ot << 32) | ~i,
                  ((u32*)&g_thr2[u]) + 1, (u32)(tv >> 32));
}

// ---------------- kernels ----------------
__global__ void k_zero() {
    size_t i = (size_t)blockIdx.x * blockDim.x + threadIdx.x;
    size_t nP = (size_t)U_SEGS * TOPK;
    size_t stride = (size_t)gridDim.x * blockDim.x;
    for (size_t j = i; j < nP; j += stride) { g_P[j] = 0ull; g_T[j] = 0ull; }
    for (size_t j = i; j < U_SEGS; j += stride) g_thr2[j] = 0ull;
    if (i < 2) g_acc[i] = 0ull;
}

// Phase 1: only items above global percentile cutoffs.
__global__ void k_phase1(const float4* __restrict__ pred4, const float4* __restrict__ targ4,
                         const int4* __restrict__ idx4,
                         const float* __restrict__ pred, const float* __restrict__ targ,
                         const int* __restrict__ idx,
                         int nq, int n, u32 qp, u32 qt) {
    int q = blockIdx.x * blockDim.x + threadIdx.x;
    if (q == 0) {                       // scalar tail (n % 4 items)
        for (int i = nq * 4; i < n; i++) {
            u32 op = ordf(pred[i]), ot = ordf(targ[i]);
            if (op >= qp || ot >= qt)
                insertItem(idx[i], op, ot, targ[i], (u32)i, op >= qp, ot >= qt);
        }
    }
    if (q >= nq) return;
    float4 pp = pred4[q];
    float4 tt = targ4[q];
    u32 op[4], ot[4];
#pragma unroll
    for (int j = 0; j < 4; j++) { op[j] = ordf((&pp.x)[j]); ot[j] = ordf((&tt.x)[j]); }
    bool any = false;
#pragma unroll
    for (int j = 0; j < 4; j++) any |= (op[j] >= qp) | (ot[j] >= qt);
    if (!any) return;
    int4 uu = idx4[q];
#pragma unroll
    for (int j = 0; j < 4; j++) {
        bool dp = op[j] >= qp, dt = ot[j] >= qt;
        if (dp | dt)
            insertItem((&uu.x)[j], op[j], ot[j], (&tt.x)[j], (u32)(q * 4 + j), dp, dt);
    }
}

// Between phases: needy flags from thresholds (thr>0 <=> board provably full of >=cutoff items)
__global__ void k_flags() {
    int u = blockIdx.x * blockDim.x + threadIdx.x;
    if (u >= U_SEGS) return;
    u64 tv = g_thr2[u];
    g_flag[u] = (u8)((((u32)tv == 0u) ? 1u : 0u) | (((u32)(tv >> 32) == 0u) ? 2u : 0u));
}

// Phase 2: below-cutoff items, only for users with a non-full board (flag != 0).
__global__ void k_phase2(const float4* __restrict__ pred4, const float4* __restrict__ targ4,
                         const int4* __restrict__ idx4,
                         const float* __restrict__ pred, const float* __restrict__ targ,
                         const int* __restrict__ idx,
                         int nq, int n, u32 qp, u32 qt) {
    int q = blockIdx.x * blockDim.x + threadIdx.x;
    if (q == 0) {
        for (int i = nq * 4; i < n; i++) {
            int u = idx[i];
            u8 f = g_flag[u];
            if (!f) continue;
            u32 op = ordf(pred[i]), ot = ordf(targ[i]);
            insertItem(u, op, ot, targ[i], (u32)i, (f & 1) && op < qp, (f & 2) && ot < qt);
        }
    }
    if (q >= nq) return;
    int4 uu = idx4[q];
    u8 f[4];
#pragma unroll
    for (int j = 0; j < 4; j++) f[j] = g_flag[(&uu.x)[j]];
    if (!(f[0] | f[1] | f[2] | f[3])) return;      // 87%^4: skip without touching pred/targ
    float4 pp = pred4[q];
    float4 tt = targ4[q];
#pragma unroll
    for (int j = 0; j < 4; j++) {
        if (!f[j]) continue;
        u32 op = ordf((&pp.x)[j]), ot = ordf((&tt.x)[j]);
        bool dp = (f[j] & 1) && op < qp;
        bool dt = (f[j] & 2) && ot < qt;
        if (dp | dt)
            insertItem((&uu.x)[j], op, ot, (&tt.x)[j], (u32)(q * 4 + j), dp, dt);
    }
}

// Per-user NDCG: rank-based (branch-free compares), vectorized board loads.
__global__ void k_user() {
    __shared__ float sw[TOPK];
    if (threadIdx.x < TOPK) sw[threadIdx.x] = c_w[threadIdx.x];
    __syncthreads();
    int u = blockIdx.x * blockDim.x + threadIdx.x;
    if (u >= U_SEGS) return;
    u64 a[TOPK], b[TOPK];
    const ulonglong2* pa = reinterpret_cast<const ulonglong2*>(&g_P[(size_t)u * TOPK]);
    const ulonglong2* pb = reinterpret_cast<const ulonglong2*>(&g_T[(size_t)u * TOPK]);
#pragma unroll
    for (int k = 0; k < TOPK / 2; k++) {
        ulonglong2 wa = __ldg(&pa[k]); a[2 * k] = wa.x; a[2 * k + 1] = wa.y;
        ulonglong2 wb = __ldg(&pb[k]); b[2 * k] = wb.x; b[2 * k + 1] = wb.y;
    }
    float dcg = 0.f, idcg = 0.f;
    bool present = false;
#pragma unroll
    for (int i = 0; i < TOPK; i++) {
        if (a[i]) {
            present = true;
            int r = 0;
#pragma unroll
            for (int j = 0; j < TOPK; j++)
                r += (a[j] > a[i]) || (a[j] == a[i] && j < i);
            dcg += sw[r] * __uint_as_float((u32)a[i]);
        }
        if (b[i]) {
            int r = 0;
#pragma unroll
            for (int j = 0; j < TOPK; j++)
                r += (b[j] > b[i]) || (b[j] == b[i] && j < i);
            u32 o = (u32)(b[i] >> 32);
            u32 bits = (o & 0x80000000u) ? (o & 0x7FFFFFFFu) : ~o;  // decode ordf
            idcg += sw[r] * __uint_as_float(bits);
        }
    }
    g_present[u] = present ? 1 : 0;
    g_ndcg[u] = (present && idcg > 0.f) ? dcg / fmaxf(idcg, 1e-12f) : 0.f;
}

// Deterministic fixed-point reduce; sample mask arrives as a 20KB by-value param.
__global__ void k_reduce(MaskParam mp) {
    __shared__ u64 ssum[256];
    __shared__ u32 scnt[256];
    u64 s = 0; u32 c = 0;
    for (int u = blockIdx.x * blockDim.x + threadIdx.x; u < U_SEGS; u += gridDim.x * blockDim.x) {
        if (((mp.w[u >> 5] >> (u & 31)) & 1u) && g_present[u]) {
            s += (u64)((double)g_ndcg[u] * 4294967296.0);
            c++;
        }
    }
    ssum[threadIdx.x] = s; scnt[threadIdx.x] = c;
    __syncthreads();
    for (int st = 128; st; st >>= 1) {
        if (threadIdx.x < st) { ssum[threadIdx.x] += ssum[threadIdx.x + st]; scnt[threadIdx.x] += scnt[threadIdx.x + st]; }
        __syncthreads();
    }
    if (threadIdx.x == 0) {
        atomicAdd(&g_acc[0], ssum[0]);
        atomicAdd(&g_acc[1], (u64)scnt[0]);
    }
}

__global__ void k_out(float* out) {
    double s = (double)g_acc[0] / 4294967296.0;
    double c = (double)g_acc[1];
    out[0] = (float)(s / (c > 1.0 ? c : 1.0));
}

// ---------------- host: exact permutation mask (data-independent => capture-time) ----------------
static void computeMask(MaskParam& mp) {
    static u32 keys[U_SEGS];
    static u32 vals[U_SEGS];
    static u32 tmpv[U_SEGS];
    static u32 ordr[U_SEGS];
    for (int i = 0; i < U_SEGS; i++) vals[i] = (u32)i;
    u32 kk0 = 0u, kk1 = 42u;
    for (int r = 0; r < 2; r++) {
        u32 nk0, nk1, sk0, sk1;
        threefry2x32(kk0, kk1, 0u, 0u, nk0, nk1);   // foldlike split: child 0 -> new key
        threefry2x32(kk0, kk1, 0u, 1u, sk0, sk1);   // child 1 -> subkey
        kk0 = nk0; kk1 = nk1;
        for (int i = 0; i < U_SEGS; i++) {
            u32 a, b;
            threefry2x32(sk0, sk1, 0u, (u32)i, a, b);
            keys[i] = a ^ b;
        }
        for (int i = 0; i < U_SEGS; i++) ordr[i] = (u32)i;
        std::stable_sort(ordr, ordr + U_SEGS,
                         [&](u32 x, u32 y) { return keys[x] < keys[y]; });
        for (int i = 0; i < U_SEGS; i++) tmpv[i] = vals[ordr[i]];
        memcpy(vals, tmpv, sizeof(tmpv));
    }
    memset(mp.w, 0, sizeof(mp.w));
    for (int i = 0; i < N_SAMPLED; i++) {
        u32 u = vals[i];
        mp.w[u >> 5] |= (1u << (u & 31));
    }
}

// ---------------- launch (7 graph nodes total) ----------------
extern "C" void kernel_launch(void* const* d_in, const int* in_sizes, int n_in,
                              void* d_out, int out_size) {
    const float* pred = (const float*)d_in[0];
    const float* targ = (const float*)d_in[1];
    const int*   idx  = (const int*)d_in[2];
    float* out = (float*)d_out;
    int n = in_sizes[0];

    MaskParam mp;
    computeMask(mp);                        // host-only, capture-time; deterministic constant

    const u32 QP = h_ordf(1.0364f);         // invPhi(0.85), pred ~ N(0,1)
    const u32 QT = h_ordf(0.85f);           // 85th pct, targets ~ U(0,1)

    k_zero<<<1024, 512>>>();

    int nq = n / 4;
    k_phase1<<<(nq + 255) / 256, 256>>>((const float4*)pred, (const float4*)targ,
                                        (const int4*)idx, pred, targ, idx, nq, n, QP, QT);
    k_flags<<<(U_SEGS + 511) / 512, 512>>>();
    k_phase2<<<(nq + 255) / 256, 256>>>((const float4*)pred, (const float4*)targ,
                                        (const int4*)idx, pred, targ, idx, nq, n, QP, QT);
    k_user<<<(U_SEGS + 255) / 256, 256>>>();
    k_reduce<<<160, 256>>>(mp);
    k_out<<<1, 1>>>(out);
}